// round 1
// baseline (speedup 1.0000x reference)
#include <cuda_runtime.h>
#include <cstdint>

#define B_DIM 4096
#define T_DIM 200
#define D_DIM 64
#define H_DIM 32
#define NEG_INF (-4294967295.0f)

// smem layout (floats): keys[200*64] | scores[200] | opart[256] | s_inv[1]
#define SMEM_FLOATS (T_DIM * D_DIM + T_DIM + 256 + 1)
#define SMEM_BYTES (SMEM_FLOATS * 4)

__global__ __launch_bounds__(256, 2)
void attn_pool_kernel(const float* __restrict__ query,
                      const float* __restrict__ keys,
                      const unsigned char* __restrict__ mask_raw,
                      const float* __restrict__ W1,
                      const float* __restrict__ b1,
                      const float* __restrict__ W2,
                      const float* __restrict__ b2,
                      float* __restrict__ out)
{
    extern __shared__ float smem[];
    float* kS     = smem;                    // 200*64
    float* scores = kS + T_DIM * D_DIM;      // 200
    float* opart  = scores + T_DIM;          // 256
    float* s_inv  = opart + 256;             // 1

    const int b    = blockIdx.x;
    const int tid  = threadIdx.x;
    const int lane = tid & 31;
    const int warp = tid >> 5;

    // ---- cooperative staging of this row's keys (float4, coalesced) ----
    {
        const float4* ksrc = reinterpret_cast<const float4*>(keys + (size_t)b * (T_DIM * D_DIM));
        float4* kdst = reinterpret_cast<float4*>(kS);
        #pragma unroll 4
        for (int i = tid; i < T_DIM * D_DIM / 4; i += 256)
            kdst[i] = ksrc[i];
    }

    // ---- mask dtype self-detection (bool-as-u8 vs int32) ----
    // If int32 with values {0,1}: every byte at offset %4 != 0 in the first
    // 256 words is zero. If uint8 random {0,1}: overwhelmingly not.
    int my_nz = 0;
    for (int w = lane; w < 256; w += 32)
        my_nz |= mask_raw[4 * w + 1] | mask_raw[4 * w + 2] | mask_raw[4 * w + 3];
    const bool mode_u8 = __any_sync(0xffffffffu, my_nz != 0);
    const int* mask_i32 = reinterpret_cast<const int*>(mask_raw);

    // ---- per-lane fused weights + query-hidden precompute ----
    // h_in = q@(W1a+W1c) + k@(W1b-W1c) + b1 ; lane j owns hidden unit j.
    float qh = b1[lane];
    unsigned long long wp[32];   // packed (wk[2p], wk[2p+1]) pairs for fma.rn.f32x2
    {
        const float* W1c = W1 + lane;
        const float* qb  = query + b * D_DIM;
        #pragma unroll 8
        for (int p = 0; p < 32; p++) {
            const int i0 = 2 * p, i1 = 2 * p + 1;
            float wa0 = W1c[i0 * H_DIM];
            float wb0 = W1c[(64 + i0) * H_DIM];
            float wc0 = W1c[(128 + i0) * H_DIM];
            float wa1 = W1c[i1 * H_DIM];
            float wb1 = W1c[(64 + i1) * H_DIM];
            float wc1 = W1c[(128 + i1) * H_DIM];
            qh = fmaf(qb[i0], wa0 + wc0, qh);
            qh = fmaf(qb[i1], wa1 + wc1, qh);
            float wk0 = wb0 - wc0;
            float wk1 = wb1 - wc1;
            asm("mov.b64 %0, {%1, %2};"
                : "=l"(wp[p]) : "r"(__float_as_uint(wk0)), "r"(__float_as_uint(wk1)));
        }
    }
    const float w2v = W2[lane];
    const float b2v = b2[0];

    __syncthreads();

    // ---- score loop: each warp scores keys t = warp, warp+8, ... ----
    for (int t = warp; t < T_DIM; t += 8) {
        uint32_t ka = (uint32_t)__cvta_generic_to_shared(kS + t * D_DIM);
        unsigned long long a0 = 0, a1 = 0, a2 = 0, a3 = 0;  // 0ull == packed (0.f, 0.f)
        #pragma unroll
        for (int c = 0; c < 16; c += 2) {
            unsigned long long k0, k1, k2, k3;
            asm volatile("ld.shared.v2.u64 {%0, %1}, [%2];"
                         : "=l"(k0), "=l"(k1) : "r"(ka + c * 16));
            asm volatile("ld.shared.v2.u64 {%0, %1}, [%2];"
                         : "=l"(k2), "=l"(k3) : "r"(ka + c * 16 + 16));
            asm("fma.rn.f32x2 %0, %1, %2, %0;" : "+l"(a0) : "l"(k0), "l"(wp[2 * c + 0]));
            asm("fma.rn.f32x2 %0, %1, %2, %0;" : "+l"(a1) : "l"(k1), "l"(wp[2 * c + 1]));
            asm("fma.rn.f32x2 %0, %1, %2, %0;" : "+l"(a2) : "l"(k2), "l"(wp[2 * c + 2]));
            asm("fma.rn.f32x2 %0, %1, %2, %0;" : "+l"(a3) : "l"(k3), "l"(wp[2 * c + 3]));
        }
        unsigned lo0, hi0, lo1, hi1, lo2, hi2, lo3, hi3;
        asm("mov.b64 {%0, %1}, %2;" : "=r"(lo0), "=r"(hi0) : "l"(a0));
        asm("mov.b64 {%0, %1}, %2;" : "=r"(lo1), "=r"(hi1) : "l"(a1));
        asm("mov.b64 {%0, %1}, %2;" : "=r"(lo2), "=r"(hi2) : "l"(a2));
        asm("mov.b64 {%0, %1}, %2;" : "=r"(lo3), "=r"(hi3) : "l"(a3));
        float h = ((__uint_as_float(lo0) + __uint_as_float(hi0)) +
                   (__uint_as_float(lo1) + __uint_as_float(hi1))) +
                  ((__uint_as_float(lo2) + __uint_as_float(hi2)) +
                   (__uint_as_float(lo3) + __uint_as_float(hi3)));
        float pre = qh + h;
        float sg  = __fdividef(1.0f, 1.0f + __expf(-pre));
        float sv  = sg * w2v;
        #pragma unroll
        for (int o = 16; o; o >>= 1)
            sv += __shfl_xor_sync(0xffffffffu, sv, o);
        if (lane == 0) {
            const int mi = b * T_DIM + t;
            const bool valid = mode_u8 ? (mask_raw[mi] != 0) : (mask_i32[mi] != 0);
            scores[t] = valid ? (sv + b2v) : NEG_INF;
        }
    }
    __syncthreads();

    // ---- softmax over 200 scores (warp 0) ----
    if (warp == 0) {
        float m = -1e38f;
        for (int t = lane; t < T_DIM; t += 32) m = fmaxf(m, scores[t]);
        #pragma unroll
        for (int o = 16; o; o >>= 1)
            m = fmaxf(m, __shfl_xor_sync(0xffffffffu, m, o));
        float s = 0.0f;
        for (int t = lane; t < T_DIM; t += 32) {
            float e = __expf(scores[t] - m);
            scores[t] = e;
            s += e;
        }
        #pragma unroll
        for (int o = 16; o; o >>= 1)
            s += __shfl_xor_sync(0xffffffffu, s, o);
        if (lane == 0) *s_inv = __fdividef(1.0f, s);
    }
    __syncthreads();

    // ---- weighted key sum: out[d] = (1/s) * sum_t prob[t] * k[t][d] ----
    {
        const int d    = tid & 63;
        const int part = tid >> 6;          // 4 partitions of 50 keys
        float acc = 0.0f;
        const float* kcol = kS + d;
        const int t0 = part * 50;
        #pragma unroll 5
        for (int t = t0; t < t0 + 50; t++)
            acc = fmaf(scores[t], kcol[t * D_DIM], acc);
        opart[tid] = acc;
    }
    __syncthreads();
    if (tid < 64) {
        float r = (opart[tid] + opart[64 + tid]) + (opart[128 + tid] + opart[192 + tid]);
        out[b * D_DIM + tid] = r * (*s_inv);
    }
}

extern "C" void kernel_launch(void* const* d_in, const int* in_sizes, int n_in,
                              void* d_out, int out_size)
{
    const float*         query = (const float*)d_in[0];
    const float*         keys  = (const float*)d_in[1];
    const unsigned char* mask  = (const unsigned char*)d_in[2];
    const float*         W1    = (const float*)d_in[3];
    const float*         b1    = (const float*)d_in[4];
    const float*         W2    = (const float*)d_in[5];
    const float*         b2    = (const float*)d_in[6];
    float* out = (float*)d_out;

    cudaFuncSetAttribute(attn_pool_kernel,
                         cudaFuncAttributeMaxDynamicSharedMemorySize, SMEM_BYTES);
    attn_pool_kernel<<<B_DIM, 256, SMEM_BYTES>>>(query, keys, mask, W1, b1, W2, b2, out);
}

// round 2
// speedup vs baseline: 1.9223x; 1.9223x over previous
#include <cuda_runtime.h>
#include <cstdint>

#define B_DIM 4096
#define T_DIM 200
#define D_DIM 64
#define H_DIM 32
#define NEG_INF (-4294967295.0f)
#define KSTR 65   // padded key-row stride in floats (65 % 32 == 1 -> conflict-free)

// shared-memory float offsets
#define OFF_K    0
#define OFF_W    (T_DIM * KSTR)           // 13000 : wk[64][32] fused W1b - W1c
#define OFF_QH   (OFF_W + 64 * 32)        // 15048 : qh[32]
#define OFF_W2   (OFF_QH + 32)            // 15080 : W2[32]
#define OFF_SC   (OFF_W2 + 32)            // 15112 : scores[200]
#define OFF_OP   (OFF_SC + T_DIM)         // 15312 : opart[256]
#define OFF_SINV (OFF_OP + 256)           // 15568
#define SMEM_FLOATS (OFF_SINV + 1)
#define SMEM_BYTES  (SMEM_FLOATS * 4)

__global__ __launch_bounds__(256, 3)
void attn_pool_kernel(const float* __restrict__ query,
                      const float* __restrict__ keys,
                      const unsigned char* __restrict__ mask_raw,
                      const float* __restrict__ W1,
                      const float* __restrict__ b1,
                      const float* __restrict__ W2,
                      const float* __restrict__ b2,
                      float* __restrict__ out)
{
    extern __shared__ float smem[];
    const int b    = blockIdx.x;
    const int tid  = threadIdx.x;
    const int lane = tid & 31;
    const uint32_t sbase = (uint32_t)__cvta_generic_to_shared(smem);

    // ---- stage keys: coalesced float4 gmem loads, scalar stores to padded rows ----
    {
        const float4* ksrc = reinterpret_cast<const float4*>(keys + (size_t)b * (T_DIM * D_DIM));
        #pragma unroll 4
        for (int i = tid; i < T_DIM * D_DIM / 4; i += 256) {
            float4 v = ksrc[i];
            int row = i >> 4, c = (i & 15) << 2;
            float* dst = smem + row * KSTR + c;
            dst[0] = v.x; dst[1] = v.y; dst[2] = v.z; dst[3] = v.w;
        }
    }

    // ---- fused key-side weights wk[d][j] = W1b[d][j] - W1c[d][j] (j contiguous) ----
    for (int idx = tid; idx < 64 * 32; idx += 256)
        smem[OFF_W + idx] = W1[2048 + idx] - W1[4096 + idx];

    if (tid < 32) smem[OFF_W2 + tid] = W2[tid];

    // ---- query-side hidden precompute: qh[j] = b1[j] + q . (W1a[:,j] + W1c[:,j]) ----
    if (tid < 32) {
        float s = b1[tid];
        const float* qb = query + b * D_DIM;
        #pragma unroll 8
        for (int d = 0; d < 64; d++)
            s = fmaf(qb[d], W1[d * 32 + tid] + W1[(128 + d) * 32 + tid], s);
        smem[OFF_QH + tid] = s;
    }

    // ---- mask dtype self-detection (bool-as-u8 vs int32), per-warp uniform ----
    int my_nz = 0;
    for (int w = lane; w < 256; w += 32)
        my_nz |= mask_raw[4 * w + 1] | mask_raw[4 * w + 2] | mask_raw[4 * w + 3];
    const bool mode_u8 = __any_sync(0xffffffffu, my_nz != 0);
    const int* mask_i32 = reinterpret_cast<const int*>(mask_raw);
    const float b2v = b2[0];

    __syncthreads();

    // ================= score phase: lane-per-key, weights broadcast from smem ========
    if (tid < T_DIM) {
        const uint32_t ka = sbase + (tid * KSTR) * 4;
        const uint32_t wa = sbase + OFF_W * 4;

        unsigned long long acc[16];
        #pragma unroll
        for (int jp = 0; jp < 16; jp += 2)
            asm("ld.shared.v2.u64 {%0,%1},[%2];"
                : "=l"(acc[jp]), "=l"(acc[jp + 1])
                : "r"(sbase + OFF_QH * 4 + jp * 8));

        #pragma unroll 1
        for (int d0 = 0; d0 < 64; d0 += 8) {
            #pragma unroll
            for (int dd = 0; dd < 8; dd++) {
                const int d = d0 + dd;
                uint32_t ku;
                asm("ld.shared.b32 %0,[%1];" : "=r"(ku) : "r"(ka + d * 4));
                unsigned long long kd2;
                asm("mov.b64 %0,{%1,%1};" : "=l"(kd2) : "r"(ku));
                #pragma unroll
                for (int jj = 0; jj < 8; jj++) {
                    unsigned long long w0, w1;
                    asm("ld.shared.v2.u64 {%0,%1},[%2];"
                        : "=l"(w0), "=l"(w1)
                        : "r"(wa + d * 128 + jj * 16));
                    asm("fma.rn.f32x2 %0,%1,%2,%0;" : "+l"(acc[2 * jj])     : "l"(kd2), "l"(w0));
                    asm("fma.rn.f32x2 %0,%1,%2,%0;" : "+l"(acc[2 * jj + 1]) : "l"(kd2), "l"(w1));
                }
            }
        }

        // epilogue: sigmoid each hidden unit, dot with W2
        float score = b2v;
        #pragma unroll
        for (int jp = 0; jp < 16; jp++) {
            unsigned lo, hi;
            asm("mov.b64 {%0,%1},%2;" : "=r"(lo), "=r"(hi) : "l"(acc[jp]));
            float h0 = __uint_as_float(lo), h1 = __uint_as_float(hi);
            float s0 = __fdividef(1.0f, 1.0f + __expf(-h0));
            float s1 = __fdividef(1.0f, 1.0f + __expf(-h1));
            score = fmaf(s0, smem[OFF_W2 + 2 * jp], score);
            score = fmaf(s1, smem[OFF_W2 + 2 * jp + 1], score);
        }
        const int mi = b * T_DIM + tid;
        const bool valid = mode_u8 ? (mask_raw[mi] != 0) : (mask_i32[mi] != 0);
        smem[OFF_SC + tid] = valid ? score : NEG_INF;
    }
    __syncthreads();

    // ---- softmax over 200 scores (warp 0); leaves exp() values in scores ----
    if (tid < 32) {
        float m = -1e38f;
        for (int t = lane; t < T_DIM; t += 32) m = fmaxf(m, smem[OFF_SC + t]);
        #pragma unroll
        for (int o = 16; o; o >>= 1)
            m = fmaxf(m, __shfl_xor_sync(0xffffffffu, m, o));
        float s = 0.0f;
        for (int t = lane; t < T_DIM; t += 32) {
            float e = __expf(smem[OFF_SC + t] - m);
            smem[OFF_SC + t] = e;
            s += e;
        }
        #pragma unroll
        for (int o = 16; o; o >>= 1)
            s += __shfl_xor_sync(0xffffffffu, s, o);
        if (lane == 0) smem[OFF_SINV] = __fdividef(1.0f, s);
    }
    __syncthreads();

    // ---- weighted key sum: out[d] = s_inv * sum_t exp_t * k[t][d] ----
    {
        const int d = tid & 63, part = tid >> 6;
        float acc = 0.0f;
        const int t0 = part * 50;
        #pragma unroll 5
        for (int t = t0; t < t0 + 50; t++)
            acc = fmaf(smem[OFF_SC + t], smem[t * KSTR + d], acc);
        smem[OFF_OP + tid] = acc;
    }
    __syncthreads();
    if (tid < 64) {
        float r = (smem[OFF_OP + tid] + smem[OFF_OP + 64 + tid]) +
                  (smem[OFF_OP + 128 + tid] + smem[OFF_OP + 192 + tid]);
        out[b * D_DIM + tid] = r * smem[OFF_SINV];
    }
}

extern "C" void kernel_launch(void* const* d_in, const int* in_sizes, int n_in,
                              void* d_out, int out_size)
{
    const float*         query = (const float*)d_in[0];
    const float*         keys  = (const float*)d_in[1];
    const unsigned char* mask  = (const unsigned char*)d_in[2];
    const float*         W1    = (const float*)d_in[3];
    const float*         b1    = (const float*)d_in[4];
    const float*         W2    = (const float*)d_in[5];
    const float*         b2    = (const float*)d_in[6];
    float* out = (float*)d_out;

    cudaFuncSetAttribute(attn_pool_kernel,
                         cudaFuncAttributeMaxDynamicSharedMemorySize, SMEM_BYTES);
    attn_pool_kernel<<<B_DIM, 256, SMEM_BYTES>>>(query, keys, mask, W1, b1, W2, b2, out);
}

// round 4
// speedup vs baseline: 2.2677x; 1.1797x over previous
#include <cuda_runtime.h>
#include <cstdint>

#define B_DIM 4096
#define T_DIM 200
#define NEG_INF (-4294967295.0f)

// dynamic smem byte offsets
#define OFF_K    0        // keys fp32, 200 rows x 256B, 16B-granule XOR swizzle
#define OFF_W    51200    // wk[64][32] fp32 (d-major, j contiguous), 8KB
#define OFF_QH   59392    // f32 qh[32]
#define OFF_W2   59520    // f32 w2[32]
#define OFF_SC   59648    // f32 scores[200]
#define OFF_OP   60448    // f32 opart[256]
#define OFF_SINV 61472    // f32
#define SMEM_BYTES 61504

__global__ __launch_bounds__(256, 3)
void attn_pool_kernel(const float* __restrict__ query,
                      const float* __restrict__ keys,
                      const unsigned char* __restrict__ mask_raw,
                      const float* __restrict__ W1,
                      const float* __restrict__ b1,
                      const float* __restrict__ W2,
                      const float* __restrict__ b2,
                      float* __restrict__ out)
{
    extern __shared__ char sm[];
    float* smf = (float*)sm;
    const int b    = blockIdx.x;
    const int tid  = threadIdx.x;
    const int lane = tid & 31;
    const int tx   = tid & 3;        // j-block: j in [8*tx, 8*tx+8)
    const int ty   = tid >> 2;       // key-block: keys 4*ty .. 4*ty+3
    uint32_t sbase;
    asm("{ .reg .u64 t; cvta.to.shared.u64 t, %1; cvt.u32.u64 %0, t; }"
        : "=r"(sbase) : "l"(sm));

    // ---- stage keys: coalesced float4 loads, XOR-swizzled granule stores ----
    {
        const float4* ksrc = (const float4*)(keys + (size_t)b * (T_DIM * 64));
        #pragma unroll 4
        for (int i = tid; i < T_DIM * 16; i += 256) {
            float4 v = ksrc[i];
            int r = i >> 4, g = i & 15;
            int gs = g ^ ((r >> 2) & 7);
            *(float4*)(sm + OFF_K + r * 256 + (gs << 4)) = v;
        }
    }

    // ---- fused key-side weights wk[d][j] = W1b[d][j] - W1c[d][j] ----
    #pragma unroll 2
    for (int idx = tid; idx < 2048; idx += 256)
        smf[OFF_W / 4 + idx] = W1[2048 + idx] - W1[4096 + idx];

    // ---- query-side hidden precompute (exact fp32) ----
    if (tid < 32) {
        float s = b1[tid];
        const float* qb = query + b * 64;
        #pragma unroll 8
        for (int d = 0; d < 64; d++)
            s = fmaf(qb[d], W1[d * 32 + tid] + W1[(128 + d) * 32 + tid], s);
        smf[OFF_QH / 4 + tid] = s;
        smf[OFF_W2 / 4 + tid] = W2[tid];
    }

    // ---- mask dtype self-detection (bool-as-u8 vs int32), warp-uniform ----
    int my_nz = 0;
    for (int w = lane; w < 256; w += 32)
        my_nz |= mask_raw[4 * w + 1] | mask_raw[4 * w + 2] | mask_raw[4 * w + 3];
    const bool mode_u8 = __any_sync(0xffffffffu, my_nz != 0);
    const int* mask_i32 = (const int*)mask_raw;
    const float b2v = b2[0];

    __syncthreads();

    // ============ score GEMM: 4 keys x 8 hidden per thread, f32x2 j-pairs ============
    if (ty < 50) {
        unsigned long long acc[16];   // acc[t*4+jp], 0ull == packed (0,0)
        #pragma unroll
        for (int i = 0; i < 16; i++) acc[i] = 0ull;

        const uint32_t kb = sbase + OFF_K + (ty * 4) * 256;
        const uint32_t wb = sbase + OFF_W + tx * 32;
        const uint32_t sw = (uint32_t)((ty & 7) << 4);

        #pragma unroll 1
        for (int ch = 0; ch < 16; ch++) {
            const uint32_t go = ((uint32_t)(ch << 4)) ^ sw;
            uint32_t kw[4][4];
            #pragma unroll
            for (int t = 0; t < 4; t++)
                asm("ld.shared.v4.b32 {%0,%1,%2,%3},[%4];"
                    : "=r"(kw[t][0]), "=r"(kw[t][1]), "=r"(kw[t][2]), "=r"(kw[t][3])
                    : "r"(kb + t * 256 + go));
            #pragma unroll
            for (int dd = 0; dd < 4; dd++) {
                unsigned long long wA, wB, wC, wD;
                const uint32_t wr = wb + (4 * ch + dd) * 128;
                asm("ld.shared.v2.u64 {%0,%1},[%2];" : "=l"(wA), "=l"(wB) : "r"(wr));
                asm("ld.shared.v2.u64 {%0,%1},[%2];" : "=l"(wC), "=l"(wD) : "r"(wr + 16));
                #pragma unroll
                for (int t = 0; t < 4; t++) {
                    unsigned long long kd;
                    asm("mov.b64 %0,{%1,%1};" : "=l"(kd) : "r"(kw[t][dd]));
                    asm("fma.rn.f32x2 %0,%1,%2,%0;" : "+l"(acc[t * 4 + 0]) : "l"(kd), "l"(wA));
                    asm("fma.rn.f32x2 %0,%1,%2,%0;" : "+l"(acc[t * 4 + 1]) : "l"(kd), "l"(wB));
                    asm("fma.rn.f32x2 %0,%1,%2,%0;" : "+l"(acc[t * 4 + 2]) : "l"(kd), "l"(wC));
                    asm("fma.rn.f32x2 %0,%1,%2,%0;" : "+l"(acc[t * 4 + 3]) : "l"(kd), "l"(wD));
                }
            }
        }

        // qh pairs for this thread's 8 j's
        unsigned long long qh2[4];
        asm("ld.shared.v2.u64 {%0,%1},[%2];"
            : "=l"(qh2[0]), "=l"(qh2[1]) : "r"(sbase + OFF_QH + tx * 32));
        asm("ld.shared.v2.u64 {%0,%1},[%2];"
            : "=l"(qh2[2]), "=l"(qh2[3]) : "r"(sbase + OFF_QH + tx * 32 + 16));
        float w2s[8];
        #pragma unroll
        for (int jj = 0; jj < 8; jj++) w2s[jj] = smf[OFF_W2 / 4 + 8 * tx + jj];

        const unsigned amask = __activemask();
        #pragma unroll
        for (int t = 0; t < 4; t++) {
            float s = 0.0f;
            #pragma unroll
            for (int jp = 0; jp < 4; jp++) {
                unsigned long long h2;
                asm("add.rn.f32x2 %0,%1,%2;" : "=l"(h2) : "l"(acc[t * 4 + jp]), "l"(qh2[jp]));
                unsigned lo, hi;
                asm("mov.b64 {%0,%1},%2;" : "=r"(lo), "=r"(hi) : "l"(h2));
                float h0 = __uint_as_float(lo), h1 = __uint_as_float(hi);
                float s0 = __fdividef(1.0f, 1.0f + __expf(-h0));
                float s1 = __fdividef(1.0f, 1.0f + __expf(-h1));
                s = fmaf(s0, w2s[2 * jp], s);
                s = fmaf(s1, w2s[2 * jp + 1], s);
            }
            s += __shfl_xor_sync(amask, s, 1);
            s += __shfl_xor_sync(amask, s, 2);
            if (tx == 0) {
                const int r = 4 * ty + t;
                const int mi = b * T_DIM + r;
                const bool valid = mode_u8 ? (mask_raw[mi] != 0) : (mask_i32[mi] != 0);
                smf[OFF_SC / 4 + r] = valid ? (s + b2v) : NEG_INF;
            }
        }
    }
    __syncthreads();

    // ---- softmax over 200 scores (warp 0) ----
    if (tid < 32) {
        float m = -1e38f;
        for (int t = lane; t < T_DIM; t += 32) m = fmaxf(m, smf[OFF_SC / 4 + t]);
        #pragma unroll
        for (int o = 16; o; o >>= 1) m = fmaxf(m, __shfl_xor_sync(0xffffffffu, m, o));
        float s = 0.0f;
        for (int t = lane; t < T_DIM; t += 32) {
            float e = __expf(smf[OFF_SC / 4 + t] - m);
            smf[OFF_SC / 4 + t] = e;
            s += e;
        }
        #pragma unroll
        for (int o = 16; o; o >>= 1) s += __shfl_xor_sync(0xffffffffu, s, o);
        if (lane == 0) smf[OFF_SINV / 4] = __fdividef(1.0f, s);
    }
    __syncthreads();

    // ---- weighted key sum: out[d] = s_inv * sum_t exp_t * k[t][d] (swizzled reads) ----
    {
        const int d = tid & 63, part = tid >> 6;
        const int ghi = d >> 2, blo = (d & 3) * 4;
        float acc = 0.0f;
        const int t0 = part * 50;
        #pragma unroll 5
        for (int t = t0; t < t0 + 50; t++) {
            int gs = ghi ^ ((t >> 2) & 7);
            float kv = *(const float*)(sm + OFF_K + t * 256 + (gs << 4) + blo);
            acc = fmaf(smf[OFF_SC / 4 + t], kv, acc);
        }
        smf[OFF_OP / 4 + tid] = acc;
    }
    __syncthreads();
    if (tid < 64) {
        float r = (smf[OFF_OP / 4 + tid] + smf[OFF_OP / 4 + 64 + tid]) +
                  (smf[OFF_OP / 4 + 128 + tid] + smf[OFF_OP / 4 + 192 + tid]);
        out[b * 64 + tid] = r * smf[OFF_SINV / 4];
    }
}

extern "C" void kernel_launch(void* const* d_in, const int* in_sizes, int n_in,
                              void* d_out, int out_size)
{
    const float*         query = (const float*)d_in[0];
    const float*         keys  = (const float*)d_in[1];
    const unsigned char* mask  = (const unsigned char*)d_in[2];
    const float*         W1    = (const float*)d_in[3];
    const float*         b1    = (const float*)d_in[4];
    const float*         W2    = (const float*)d_in[5];
    const float*         b2    = (const float*)d_in[6];
    float* out = (float*)d_out;

    cudaFuncSetAttribute(attn_pool_kernel,
                         cudaFuncAttributeMaxDynamicSharedMemorySize, SMEM_BYTES);
    attn_pool_kernel<<<B_DIM, 256, SMEM_BYTES>>>(query, keys, mask, W1, b1, W2, b2, out);
}

// round 5
// speedup vs baseline: 3.0236x; 1.3333x over previous
#include <cuda_runtime.h>
#include <cstdint>

#define B_DIM 4096
#define T_DIM 200
#define NEG_INF (-4294967295.0f)

// dynamic smem byte offsets (all 16B-aligned)
#define OFF_K    0        // keys fp32, 200 rows x 256B, 16B-granule XOR swizzle
#define OFF_W    51200    // wk[64][32] fp32 (d-major, j contiguous), 8KB
#define OFF_QH   59392    // f32 qh[32] (precomputed, per-b)
#define OFF_W2   59520    // f32 w2[32]
#define OFF_SC   59648    // f32 scores[200]
#define OFF_OP   60448    // u64 opart[8][32] (f32x2 partial sums), 2KB
#define OFF_SINV 62496    // f32
#define SMEM_BYTES 62512

__device__ float g_wk[2048];        // W1b - W1c, j contiguous
__device__ float g_qh[B_DIM * 32];  // b1 + q @ (W1a + W1c)

// ---------------- setup kernel: batch-invariant + query-side precompute ----------------
__global__ __launch_bounds__(256)
void setup_kernel(const float* __restrict__ query,
                  const float* __restrict__ W1,
                  const float* __restrict__ b1)
{
    __shared__ float wq[2048];      // W1a + W1c
    __shared__ float qs[8][64];
    const int tid = threadIdx.x;
    #pragma unroll 2
    for (int i = tid; i < 2048; i += 256) {
        float a = W1[i], c = W1[4096 + i];
        wq[i] = a + c;
        if (blockIdx.x == 0) g_wk[i] = W1[2048 + i] - c;
    }
    const int b0 = blockIdx.x * 8;
    for (int i = tid; i < 512; i += 256)
        qs[i >> 6][i & 63] = query[(size_t)b0 * 64 + i];
    __syncthreads();
    const int j = tid & 31, bl = tid >> 5;
    float s = b1[j];
    #pragma unroll 16
    for (int d = 0; d < 64; d++)
        s = fmaf(qs[bl][d], wq[d * 32 + j], s);
    g_qh[(b0 + bl) * 32 + j] = s;
}

// ---------------- main kernel ----------------
__global__ __launch_bounds__(256, 3)
void attn_pool_kernel(const float* __restrict__ keys,
                      const unsigned char* __restrict__ mask_raw,
                      const float* __restrict__ W2,
                      const float* __restrict__ b2,
                      float* __restrict__ out)
{
    extern __shared__ char sm[];
    float* smf = (float*)sm;
    const int b    = blockIdx.x;
    const int tid  = threadIdx.x;
    const int lane = tid & 31;
    const int tx   = tid & 3;        // j-block: j in [8*tx, 8*tx+8)
    const int ty   = tid >> 2;       // key-block: keys 4*ty .. 4*ty+3
    uint32_t sbase;
    asm("{ .reg .u64 t; cvta.to.shared.u64 t, %1; cvt.u32.u64 %0, t; }"
        : "=r"(sbase) : "l"(sm));

    // ---- async staging: keys (swizzled), wk, qh row, w2 ----
    {
        const char* ksrc = (const char*)(keys + (size_t)b * (T_DIM * 64));
        #pragma unroll 4
        for (int i = tid; i < T_DIM * 16; i += 256) {
            int r = i >> 4, g = i & 15;
            int gs = g ^ ((r >> 2) & 7);
            uint32_t dst = sbase + OFF_K + r * 256 + (gs << 4);
            asm volatile("cp.async.cg.shared.global [%0], [%1], 16;"
                         :: "r"(dst), "l"(ksrc + i * 16));
        }
        #pragma unroll
        for (int i = tid; i < 512; i += 256)
            asm volatile("cp.async.cg.shared.global [%0], [%1], 16;"
                         :: "r"(sbase + OFF_W + i * 16), "l"((const char*)g_wk + i * 16));
        if (tid < 8)
            asm volatile("cp.async.cg.shared.global [%0], [%1], 16;"
                         :: "r"(sbase + OFF_QH + tid * 16),
                            "l"((const char*)(g_qh + b * 32) + tid * 16));
        else if (tid < 16)
            asm volatile("cp.async.cg.shared.global [%0], [%1], 16;"
                         :: "r"(sbase + OFF_W2 + (tid - 8) * 16),
                            "l"((const char*)W2 + (tid - 8) * 16));
        asm volatile("cp.async.commit_group;" ::: "memory");
    }

    // ---- overlapped with async wait: mask dtype detect + mask/b2 prefetch ----
    int my_nz = 0;
    #pragma unroll
    for (int w = lane; w < 256; w += 32)
        my_nz |= mask_raw[4 * w + 1] | mask_raw[4 * w + 2] | mask_raw[4 * w + 3];
    const bool mode_u8 = __any_sync(0xffffffffu, my_nz != 0);
    const int* mask_i32 = (const int*)mask_raw;
    const float b2v = __ldg(b2);

    int mvalid = 0;
    if (tx == 0 && ty < 50) {
        #pragma unroll
        for (int t = 0; t < 4; t++) {
            const int mi = b * T_DIM + 4 * ty + t;
            const bool v = mode_u8 ? (mask_raw[mi] != 0) : (mask_i32[mi] != 0);
            mvalid |= (int)v << t;
        }
    }

    asm volatile("cp.async.wait_group 0;" ::: "memory");
    __syncthreads();

    // ============ score GEMM: 4 keys x 8 hidden per thread, f32x2 j-pairs ============
    if (ty < 50) {
        unsigned long long acc[16];
        #pragma unroll
        for (int i = 0; i < 16; i++) acc[i] = 0ull;

        const uint32_t kb = sbase + OFF_K + (ty * 4) * 256;
        const uint32_t wb = sbase + OFF_W + tx * 32;
        const uint32_t sw = (uint32_t)((ty & 7) << 4);

        #pragma unroll 1
        for (int ch = 0; ch < 16; ch++) {
            const uint32_t go = ((uint32_t)(ch << 4)) ^ sw;
            uint32_t kw[4][4];
            #pragma unroll
            for (int t = 0; t < 4; t++)
                asm("ld.shared.v4.b32 {%0,%1,%2,%3},[%4];"
                    : "=r"(kw[t][0]), "=r"(kw[t][1]), "=r"(kw[t][2]), "=r"(kw[t][3])
                    : "r"(kb + t * 256 + go));
            #pragma unroll
            for (int dd = 0; dd < 4; dd++) {
                unsigned long long wA, wB, wC, wD;
                const uint32_t wr = wb + (4 * ch + dd) * 128;
                asm("ld.shared.v2.u64 {%0,%1},[%2];" : "=l"(wA), "=l"(wB) : "r"(wr));
                asm("ld.shared.v2.u64 {%0,%1},[%2];" : "=l"(wC), "=l"(wD) : "r"(wr + 16));
                #pragma unroll
                for (int t = 0; t < 4; t++) {
                    unsigned long long kd;
                    asm("mov.b64 %0,{%1,%1};" : "=l"(kd) : "r"(kw[t][dd]));
                    asm("fma.rn.f32x2 %0,%1,%2,%0;" : "+l"(acc[t * 4 + 0]) : "l"(kd), "l"(wA));
                    asm("fma.rn.f32x2 %0,%1,%2,%0;" : "+l"(acc[t * 4 + 1]) : "l"(kd), "l"(wB));
                    asm("fma.rn.f32x2 %0,%1,%2,%0;" : "+l"(acc[t * 4 + 2]) : "l"(kd), "l"(wC));
                    asm("fma.rn.f32x2 %0,%1,%2,%0;" : "+l"(acc[t * 4 + 3]) : "l"(kd), "l"(wD));
                }
            }
        }

        unsigned long long qh2[4];
        asm("ld.shared.v2.u64 {%0,%1},[%2];"
            : "=l"(qh2[0]), "=l"(qh2[1]) : "r"(sbase + OFF_QH + tx * 32));
        asm("ld.shared.v2.u64 {%0,%1},[%2];"
            : "=l"(qh2[2]), "=l"(qh2[3]) : "r"(sbase + OFF_QH + tx * 32 + 16));
        float w2s[8];
        #pragma unroll
        for (int jj = 0; jj < 8; jj++) w2s[jj] = smf[OFF_W2 / 4 + 8 * tx + jj];

        const unsigned amask = __activemask();
        #pragma unroll
        for (int t = 0; t < 4; t++) {
            float s = 0.0f;
            #pragma unroll
            for (int jp = 0; jp < 4; jp++) {
                unsigned long long h2;
                asm("add.rn.f32x2 %0,%1,%2;" : "=l"(h2) : "l"(acc[t * 4 + jp]), "l"(qh2[jp]));
                unsigned lo, hi;
                asm("mov.b64 {%0,%1},%2;" : "=r"(lo), "=r"(hi) : "l"(h2));
                float h0 = __uint_as_float(lo), h1 = __uint_as_float(hi);
                float s0 = __fdividef(1.0f, 1.0f + __expf(-h0));
                float s1 = __fdividef(1.0f, 1.0f + __expf(-h1));
                s = fmaf(s0, w2s[2 * jp], s);
                s = fmaf(s1, w2s[2 * jp + 1], s);
            }
            s += __shfl_xor_sync(amask, s, 1);
            s += __shfl_xor_sync(amask, s, 2);
            if (tx == 0) {
                const int r = 4 * ty + t;
                smf[OFF_SC / 4 + r] = ((mvalid >> t) & 1) ? (s + b2v) : NEG_INF;
            }
        }
    }
    __syncthreads();

    // ---- softmax over 200 scores (warp 0) ----
    if (tid < 32) {
        float m = -1e38f;
        for (int t = lane; t < T_DIM; t += 32) m = fmaxf(m, smf[OFF_SC / 4 + t]);
        #pragma unroll
        for (int o = 16; o; o >>= 1) m = fmaxf(m, __shfl_xor_sync(0xffffffffu, m, o));
        float s = 0.0f;
        for (int t = lane; t < T_DIM; t += 32) {
            float e = __expf(smf[OFF_SC / 4 + t] - m);
            smf[OFF_SC / 4 + t] = e;
            s += e;
        }
        #pragma unroll
        for (int o = 16; o; o >>= 1) s += __shfl_xor_sync(0xffffffffu, s, o);
        if (lane == 0) smf[OFF_SINV / 4] = __fdividef(1.0f, s);
    }
    __syncthreads();

    // ---- weighted key sum, f32x2 over d-pairs: warp w handles keys [25w, 25w+25) ----
    {
        const int part = tid >> 5;             // warp id 0..7
        unsigned long long acc = 0ull;
        const uint32_t kbase = sbase + OFF_K;
        const int t0 = part * 25;
        #pragma unroll 5
        for (int t = t0; t < t0 + 25; t++) {
            float p = smf[OFF_SC / 4 + t];
            unsigned long long pd;
            asm("mov.b64 %0,{%1,%1};" : "=l"(pd) : "r"(__float_as_uint(p)));
            int gs = (lane >> 1) ^ ((t >> 2) & 7);
            unsigned long long kv;
            asm("ld.shared.b64 %0,[%1];" : "=l"(kv)
                : "r"(kbase + t * 256 + (gs << 4) + ((lane & 1) << 3)));
            asm("fma.rn.f32x2 %0,%1,%2,%0;" : "+l"(acc) : "l"(kv), "l"(pd));
        }
        asm volatile("st.shared.b64 [%0],%1;"
                     :: "r"(sbase + OFF_OP + part * 256 + lane * 8), "l"(acc));
    }
    __syncthreads();
    if (tid < 64) {
        float r = 0.0f;
        #pragma unroll
        for (int p = 0; p < 8; p++)
            r += smf[(OFF_OP + p * 256) / 4 + tid];
        out[b * 64 + tid] = r * smf[OFF_SINV / 4];
    }
}

extern "C" void kernel_launch(void* const* d_in, const int* in_sizes, int n_in,
                              void* d_out, int out_size)
{
    const float*         query = (const float*)d_in[0];
    const float*         keys  = (const float*)d_in[1];
    const unsigned char* mask  = (const unsigned char*)d_in[2];
    const float*         W1    = (const float*)d_in[3];
    const float*         b1    = (const float*)d_in[4];
    const float*         W2    = (const float*)d_in[5];
    const float*         b2    = (const float*)d_in[6];
    float* out = (float*)d_out;

    setup_kernel<<<B_DIM / 8, 256>>>(query, W1, b1);
    cudaFuncSetAttribute(attn_pool_kernel,
                         cudaFuncAttributeMaxDynamicSharedMemorySize, SMEM_BYTES);
    attn_pool_kernel<<<B_DIM, 256, SMEM_BYTES>>>(keys, mask, W2, b2, out);
}